// round 4
// baseline (speedup 1.0000x reference)
#include <cuda_runtime.h>
#include <cstdint>

#define BATCH   2048
#define NCLS    50257
#define KPOS    20
#define THREADS 256
#define SLICES  8
#define CHUNK   1571               // ceil(max_n4 / SLICES), n4 <= 12564
#define GRID    (BATCH * SLICES)

// Scratch (device globals => allocation-free)
__device__ float g_part[GRID];     // per-chunk partial sums (log2 domain)
__device__ float g_a[BATCH];       // per-row: pos/K - w*corr
__device__ float g_w[BATCH];       // per-row: 1/(NCLS - uniq)
__device__ int   g_ticket;

__device__ __forceinline__ float ex2f(float x) {
    float r; asm("ex2.approx.ftz.f32 %0, %1;" : "=f"(r) : "f"(x)); return r;
}
__device__ __forceinline__ float lg2f(float x) {
    float r; asm("lg2.approx.ftz.f32 %0, %1;" : "=f"(r) : "f"(x)); return r;
}

#define L2E 1.4426950408889634f
#define LN2 0.6931471805599453f

// log(sigmoid(z)) = -ln2 * log2(1 + 2^(-z*log2e))  (inputs ~N(0,1))
__device__ __forceinline__ float log_sig(float z) {
    return -LN2 * lg2f(1.0f + ex2f(-z * L2E));
}

__global__ __launch_bounds__(THREADS, 8) void mlsml_kernel(
    const float* __restrict__ x,    // [BATCH, NCLS]
    const int*   __restrict__ tgt,  // [BATCH, KPOS]
    float*       __restrict__ out)  // [1]
{
    const int chunk = blockIdx.x;
    const int row   = chunk >> 3;          // SLICES == 8
    const int sl    = chunk & 7;
    const int tid   = threadIdx.x;
    const float* __restrict__ xr = x + (size_t)row * NCLS;

    // Row base offset mod 4 == row mod 4 (50257 % 4 == 1) -> peel to 16B align.
    const int head = (4 - (row & 3)) & 3;
    const int n4   = (NCLS - head) >> 2;
    const int rem  = (NCLS - head) & 3;

    // s2: partial sum of log2(1 + exp(x)) for this slice (log2 domain)
    float s2 = 0.0f;
    if (sl == 0 && tid < head)
        s2 += lg2f(1.0f + ex2f(xr[tid] * L2E));
    if (sl == SLICES - 1 && tid < rem)
        s2 += lg2f(1.0f + ex2f(xr[head + 4 * n4 + tid] * L2E));

    const int lo = sl * CHUNK;
    const int hi = min(n4, lo + CHUNK);
    const float4* __restrict__ p = (const float4*)(xr + head);
    #pragma unroll 4
    for (int i = lo + tid; i < hi; i += THREADS) {
        float4 v = __ldcs(p + i);   // streaming: evict-first
        float t0 = ex2f(v.x * L2E);
        float t1 = ex2f(v.y * L2E);
        float t2 = ex2f(v.z * L2E);
        float t3 = ex2f(v.w * L2E);
        float pr = ((1.0f + t0) * (1.0f + t1)) * ((1.0f + t2) * (1.0f + t3));
        s2 += lg2f(pr);
    }

    // Block reduction of s2
    #pragma unroll
    for (int o = 16; o > 0; o >>= 1)
        s2 += __shfl_down_sync(0xffffffffu, s2, o);

    __shared__ float red[THREADS / 32];
    __shared__ int   sIsLast;
    const int lane = tid & 31, wid = tid >> 5;
    if (lane == 0) red[wid] = s2;
    __syncthreads();

    if (wid == 0) {
        float S2 = (lane < THREADS / 32) ? red[lane] : 0.0f;
        #pragma unroll
        for (int o = 16; o > 0; o >>= 1)
            S2 += __shfl_down_sync(0xffffffffu, S2, o);
        if (lane == 0) g_part[chunk] = S2;

        // Slice 0 also computes the row epilogue (warp-parallel over K=20)
        if (sl == 0) {
            float pos = 0.0f, corr = 0.0f;
            int   uq  = 0;
            if (lane < KPOS) {
                int   idx = __ldg(tgt + row * KPOS + lane);
                float v   = __ldg(xr + idx);
                pos = log_sig(v);
                unsigned m = __match_any_sync(0x000FFFFFu, idx);
                if ((m & (unsigned)(-(int)m)) == (1u << lane)) {
                    corr = log_sig(-v);
                    uq   = 1;
                }
            }
            #pragma unroll
            for (int o = 16; o > 0; o >>= 1) {
                pos  += __shfl_down_sync(0xffffffffu, pos,  o);
                corr += __shfl_down_sync(0xffffffffu, corr, o);
                uq   += __shfl_down_sync(0xffffffffu, uq,   o);
            }
            if (lane == 0) {
                float w = 1.0f / (float)(NCLS - uq);
                g_w[row] = w;
                g_a[row] = pos * (1.0f / KPOS) - corr * w;
            }
        }

        if (lane == 0) {
            __threadfence();
            int ticket = atomicAdd(&g_ticket, 1);
            sIsLast = (ticket == GRID - 1);
        }
    }
    __syncthreads();

    // Last CTA: deterministic fixed-order final reduction
    if (sIsLast) {
        __threadfence();
        float acc = 0.0f;
        for (int r = tid; r < BATCH; r += THREADS) {
            float ss = 0.0f;
            #pragma unroll
            for (int j = 0; j < SLICES; j++)
                ss += __ldcg(&g_part[r * SLICES + j]);
            float S = -LN2 * ss;   // sum log_sigmoid(-x) over row r
            acc += __ldcg(&g_a[r]) + __ldcg(&g_w[r]) * S;
        }
        #pragma unroll
        for (int o = 16; o > 0; o >>= 1)
            acc += __shfl_down_sync(0xffffffffu, acc, o);
        if (lane == 0) red[wid] = acc;
        __syncthreads();
        if (tid == 0) {
            float S = 0.0f;
            #pragma unroll
            for (int w = 0; w < THREADS / 32; w++) S += red[w];
            out[0] = -S / (float)BATCH;
            g_ticket = 0;  // reset for next graph replay
        }
    }
}

extern "C" void kernel_launch(void* const* d_in, const int* in_sizes, int n_in,
                              void* d_out, int out_size) {
    const float* x   = (const float*)d_in[0];
    const int*   tgt = (const int*)d_in[1];
    float*       out = (float*)d_out;
    mlsml_kernel<<<GRID, THREADS>>>(x, tgt, out);
}

// round 5
// speedup vs baseline: 1.0230x; 1.0230x over previous
#include <cuda_runtime.h>
#include <cstdint>

#define BATCH    2048
#define NCLS     50257
#define KPOS     20
#define THREADS  256
#define F4_CHUNK 1536                    // float4 per chunk = 6 iters * 256 thr
#define E_CHUNK  (F4_CHUNK * 4)          // 6144 elements per chunk
#define TOTAL_F4 25731584                // BATCH*NCLS/4
#define NCHUNKS  16753                   // ceil(TOTAL_F4 / F4_CHUNK)

// Scratch (device globals => allocation-free)
__device__ float g_pA[NCHUNKS];          // chunk partial, first-row part (log2 domain)
__device__ float g_pB[NCHUNKS];          // chunk partial, second-row part (log2 domain)
__device__ float g_a[BATCH];             // per-row: pos/K - w*corr
__device__ float g_w[BATCH];             // per-row: 1/(NCLS - uniq)
__device__ int   g_ticket;

__device__ __forceinline__ float ex2f(float x) {
    float r; asm("ex2.approx.ftz.f32 %0, %1;" : "=f"(r) : "f"(x)); return r;
}
__device__ __forceinline__ float lg2f(float x) {
    float r; asm("lg2.approx.ftz.f32 %0, %1;" : "=f"(r) : "f"(x)); return r;
}

#define L2E 1.4426950408889634f
#define LN2 0.6931471805599453f

// log(sigmoid(z)) = -ln2 * log2(1 + 2^(-z*log2e))  (inputs ~N(0,1))
__device__ __forceinline__ float log_sig(float z) {
    return -LN2 * lg2f(1.0f + ex2f(-z * L2E));
}
// log2(1 + exp(x))
__device__ __forceinline__ float sp2(float x) {
    return lg2f(1.0f + ex2f(x * L2E));
}

__global__ __launch_bounds__(THREADS, 8) void mlsml_kernel(
    const float* __restrict__ x,    // [BATCH, NCLS] viewed flat
    const int*   __restrict__ tgt,  // [BATCH, KPOS]
    float*       __restrict__ out)  // [1]
{
    const int c   = blockIdx.x;
    const int tid = threadIdx.x;

    const unsigned base_e  = (unsigned)c * E_CHUNK;
    const int      base_f4 = c * F4_CHUNK;
    const int      n_f4    = min(F4_CHUNK, TOTAL_F4 - base_f4);
    const unsigned rowS    = base_e / NCLS;
    const unsigned bnd     = (rowS + 1u) * NCLS;      // first elem of next row
    const bool     crossing = (bnd < base_e + (unsigned)(4 * n_f4));

    const float4* __restrict__ p = (const float4*)x + base_f4;

    float sA = 0.0f, sB = 0.0f;   // log2-domain partials (rowS / rowS+1)

    if (!crossing && n_f4 == F4_CHUNK) {
        // Fast path: fixed 6-deep unroll, all loads independent.
        float4 v0 = __ldcs(p + 0 * THREADS + tid);
        float4 v1 = __ldcs(p + 1 * THREADS + tid);
        float4 v2 = __ldcs(p + 2 * THREADS + tid);
        float4 v3 = __ldcs(p + 3 * THREADS + tid);
        float4 v4 = __ldcs(p + 4 * THREADS + tid);
        float4 v5 = __ldcs(p + 5 * THREADS + tid);
        #define PROD4(v) (((1.0f + ex2f((v).x * L2E)) * (1.0f + ex2f((v).y * L2E))) * \
                          ((1.0f + ex2f((v).z * L2E)) * (1.0f + ex2f((v).w * L2E))))
        sA += lg2f(PROD4(v0));
        sA += lg2f(PROD4(v1));
        sA += lg2f(PROD4(v2));
        sA += lg2f(PROD4(v3));
        sA += lg2f(PROD4(v4));
        sA += lg2f(PROD4(v5));
        #undef PROD4
    } else {
        // Slow path: boundary-crossing or final partial chunk (per-element routing).
        for (int i = tid; i < n_f4; i += THREADS) {
            float4 v = __ldcs(p + i);
            unsigned e = base_e + 4u * (unsigned)i;
            float t0 = sp2(v.x), t1 = sp2(v.y), t2 = sp2(v.z), t3 = sp2(v.w);
            if (e + 0 < bnd) sA += t0; else sB += t0;
            if (e + 1 < bnd) sA += t1; else sB += t1;
            if (e + 2 < bnd) sA += t2; else sB += t2;
            if (e + 3 < bnd) sA += t3; else sB += t3;
        }
    }

    // Block reduction of (sA, sB)
    #pragma unroll
    for (int o = 16; o > 0; o >>= 1) {
        sA += __shfl_down_sync(0xffffffffu, sA, o);
        sB += __shfl_down_sync(0xffffffffu, sB, o);
    }
    __shared__ float redA[THREADS / 32], redB[THREADS / 32];
    __shared__ int   sIsLast;
    const int lane = tid & 31, wid = tid >> 5;
    if (lane == 0) { redA[wid] = sA; redB[wid] = sB; }
    __syncthreads();

    if (wid == 0) {
        float SA = (lane < THREADS / 32) ? redA[lane] : 0.0f;
        float SB = (lane < THREADS / 32) ? redB[lane] : 0.0f;
        #pragma unroll
        for (int o = 4; o > 0; o >>= 1) {
            SA += __shfl_down_sync(0xffffffffu, SA, o);
            SB += __shfl_down_sync(0xffffffffu, SB, o);
        }
        if (lane == 0) { g_pA[c] = SA; g_pB[c] = SB; }

        // CTAs 0..BATCH-1 also handle row c's target epilogue (warp-parallel K=20)
        if (c < BATCH) {
            const float* __restrict__ xr = x + (size_t)c * NCLS;
            float pos = 0.0f, corr = 0.0f;
            int   uq  = 0;
            if (lane < KPOS) {
                int   idx = __ldg(tgt + c * KPOS + lane);
                float v   = __ldg(xr + idx);
                pos = log_sig(v);
                unsigned m = __match_any_sync(0x000FFFFFu, idx);
                if ((m & (unsigned)(-(int)m)) == (1u << lane)) {
                    corr = log_sig(-v);
                    uq   = 1;
                }
            }
            #pragma unroll
            for (int o = 16; o > 0; o >>= 1) {
                pos  += __shfl_down_sync(0xffffffffu, pos,  o);
                corr += __shfl_down_sync(0xffffffffu, corr, o);
                uq   += __shfl_down_sync(0xffffffffu, uq,   o);
            }
            if (lane == 0) {
                float w = 1.0f / (float)(NCLS - uq);
                g_w[c] = w;
                g_a[c] = pos * (1.0f / KPOS) - corr * w;
            }
        }

        if (lane == 0) {
            __threadfence();
            int ticket = atomicAdd(&g_ticket, 1);
            sIsLast = (ticket == NCHUNKS - 1);
        }
    }
    __syncthreads();

    // Last CTA: deterministic fixed-order per-row reassembly + final mean
    if (sIsLast) {
        __threadfence();
        float acc = 0.0f;
        for (int r = tid; r < BATCH; r += THREADS) {
            unsigned e0 = (unsigned)r * NCLS;
            unsigned e1 = e0 + NCLS;
            int c0 = (int)(e0 / E_CHUNK);
            int c1 = (int)((e1 - 1u) / E_CHUNK);
            // first chunk: if it starts before e0, row r's part is its B-half
            float s = ((unsigned)c0 * E_CHUNK < e0) ? __ldcg(&g_pB[c0])
                                                    : __ldcg(&g_pA[c0]);
            for (int cc = c0 + 1; cc <= c1; cc++)
                s += __ldcg(&g_pA[cc]);
            float S = -LN2 * s;   // sum log_sigmoid(-x) over row r
            acc += __ldcg(&g_a[r]) + __ldcg(&g_w[r]) * S;
        }
        #pragma unroll
        for (int o = 16; o > 0; o >>= 1)
            acc += __shfl_down_sync(0xffffffffu, acc, o);
        if (lane == 0) redA[wid] = acc;
        __syncthreads();
        if (tid == 0) {
            float S = 0.0f;
            #pragma unroll
            for (int w = 0; w < THREADS / 32; w++) S += redA[w];
            out[0] = -S / (float)BATCH;
            g_ticket = 0;  // reset for next graph replay
        }
    }
}

extern "C" void kernel_launch(void* const* d_in, const int* in_sizes, int n_in,
                              void* d_out, int out_size) {
    const float* x   = (const float*)d_in[0];
    const int*   tgt = (const int*)d_in[1];
    float*       out = (float*)d_out;
    mlsml_kernel<<<NCHUNKS, THREADS>>>(x, tgt, out);
}

// round 6
// speedup vs baseline: 1.1434x; 1.1177x over previous
#include <cuda_runtime.h>
#include <cstdint>

#define BATCH   2048
#define NCLS    50257
#define KPOS    20
#define THREADS 256
#define QPR     4                    // quarters per row
#define QF4     3141                 // float4 per quarter (4*3141 >= max n4 12564)
#define GRID    (BATCH * QPR)        // 8192 CTAs

// Scratch (device globals => allocation-free)
__device__ float g_q[GRID];          // per-quarter partial sums (log2 domain)
__device__ float g_a[BATCH];         // per-row: pos/K - w*corr
__device__ float g_w[BATCH];         // per-row: 1/(NCLS - uniq)
__device__ int   g_ticket;

__device__ __forceinline__ float ex2f(float x) {
    float r; asm("ex2.approx.ftz.f32 %0, %1;" : "=f"(r) : "f"(x)); return r;
}
__device__ __forceinline__ float lg2f(float x) {
    float r; asm("lg2.approx.ftz.f32 %0, %1;" : "=f"(r) : "f"(x)); return r;
}

#define L2E 1.4426950408889634f
#define LN2 0.6931471805599453f

// log(sigmoid(z)) = -ln2 * log2(1 + 2^(-z*log2e))  (inputs ~N(0,1))
__device__ __forceinline__ float log_sig(float z) {
    return -LN2 * lg2f(1.0f + ex2f(-z * L2E));
}

__global__ __launch_bounds__(THREADS, 8) void mlsml_kernel(
    const float* __restrict__ x,    // [BATCH, NCLS]
    const int*   __restrict__ tgt,  // [BATCH, KPOS]
    float*       __restrict__ out)  // [1]
{
    const int bid = blockIdx.x;
    const int row = bid >> 2;
    const int q   = bid & 3;
    const int tid = threadIdx.x;
    const float* __restrict__ xr = x + (size_t)row * NCLS;

    // Row base offset mod 4 == row mod 4 (50257 % 4 == 1) -> peel to 16B align.
    const int head = (4 - (row & 3)) & 3;
    const int n4   = (NCLS - head) >> 2;
    const int rem  = (NCLS - head) & 3;

    // s2: partial sum of log2(1 + exp(x)) for this quarter (log2 domain)
    float s2 = 0.0f;
    if (q == 0 && tid < head)
        s2 += lg2f(1.0f + ex2f(xr[tid] * L2E));
    if (q == QPR - 1 && tid < rem)
        s2 += lg2f(1.0f + ex2f(xr[head + 4 * n4 + tid] * L2E));

    const int lo = q * QF4;
    const int hi = min(n4, lo + QF4);
    const float4* __restrict__ p = (const float4*)(xr + head);

    #define PROD4(v) (((1.0f + ex2f((v).x * L2E)) * (1.0f + ex2f((v).y * L2E))) * \
                      ((1.0f + ex2f((v).z * L2E)) * (1.0f + ex2f((v).w * L2E))))
    int i = lo + tid;
    for (; i + 3 * THREADS < hi; i += 4 * THREADS) {
        float4 v0 = __ldcs(p + i);
        float4 v1 = __ldcs(p + i + THREADS);
        float4 v2 = __ldcs(p + i + 2 * THREADS);
        float4 v3 = __ldcs(p + i + 3 * THREADS);
        s2 += lg2f(PROD4(v0));
        s2 += lg2f(PROD4(v1));
        s2 += lg2f(PROD4(v2));
        s2 += lg2f(PROD4(v3));
    }
    for (; i < hi; i += THREADS) {
        float4 v = __ldcs(p + i);
        s2 += lg2f(PROD4(v));
    }
    #undef PROD4

    // Block reduction of s2
    #pragma unroll
    for (int o = 16; o > 0; o >>= 1)
        s2 += __shfl_down_sync(0xffffffffu, s2, o);

    __shared__ float red[THREADS / 32];
    __shared__ int   sIsLast;
    const int lane = tid & 31, wid = tid >> 5;
    if (lane == 0) red[wid] = s2;
    __syncthreads();

    if (wid == 0) {
        float S2 = (lane < THREADS / 32) ? red[lane] : 0.0f;
        #pragma unroll
        for (int o = 4; o > 0; o >>= 1)
            S2 += __shfl_down_sync(0xffffffffu, S2, o);
        if (lane == 0) g_q[bid] = S2;

        // Quarter 0 also computes the row target epilogue (warp-parallel K=20)
        if (q == 0) {
            float pos = 0.0f, corr = 0.0f;
            int   uq  = 0;
            if (lane < KPOS) {
                int   idx = __ldg(tgt + row * KPOS + lane);
                float v   = __ldg(xr + idx);
                pos = log_sig(v);
                unsigned m = __match_any_sync(0x000FFFFFu, idx);
                if ((m & (unsigned)(-(int)m)) == (1u << lane)) {
                    corr = log_sig(-v);
                    uq   = 1;
                }
            }
            #pragma unroll
            for (int o = 16; o > 0; o >>= 1) {
                pos  += __shfl_down_sync(0xffffffffu, pos,  o);
                corr += __shfl_down_sync(0xffffffffu, corr, o);
                uq   += __shfl_down_sync(0xffffffffu, uq,   o);
            }
            if (lane == 0) {
                float w = 1.0f / (float)(NCLS - uq);
                g_w[row] = w;
                g_a[row] = pos * (1.0f / KPOS) - corr * w;
            }
        }

        if (lane == 0) {
            __threadfence();
            int ticket = atomicAdd(&g_ticket, 1);
            sIsLast = (ticket == GRID - 1);
        }
    }
    __syncthreads();

    // Last CTA: deterministic fixed-order per-row reassembly + final mean
    if (sIsLast) {
        __threadfence();
        float acc = 0.0f;
        for (int r = tid; r < BATCH; r += THREADS) {
            float ss = (__ldcg(&g_q[4 * r + 0]) + __ldcg(&g_q[4 * r + 1])) +
                       (__ldcg(&g_q[4 * r + 2]) + __ldcg(&g_q[4 * r + 3]));
            float S = -LN2 * ss;   // sum log_sigmoid(-x) over row r
            acc += __ldcg(&g_a[r]) + __ldcg(&g_w[r]) * S;
        }
        #pragma unroll
        for (int o = 16; o > 0; o >>= 1)
            acc += __shfl_down_sync(0xffffffffu, acc, o);
        if (lane == 0) red[wid] = acc;
        __syncthreads();
        if (tid == 0) {
            float S = 0.0f;
            #pragma unroll
            for (int w = 0; w < THREADS / 32; w++) S += red[w];
            out[0] = -S / (float)BATCH;
            g_ticket = 0;  // reset for next graph replay
        }
    }
}

extern "C" void kernel_launch(void* const* d_in, const int* in_sizes, int n_in,
                              void* d_out, int out_size) {
    const float* x   = (const float*)d_in[0];
    const int*   tgt = (const int*)d_in[1];
    float*       out = (float*)d_out;
    mlsml_kernel<<<GRID, THREADS>>>(x, tgt, out);
}